// round 11
// baseline (speedup 1.0000x reference)
#include <cuda_runtime.h>
#include <cuda_fp16.h>

#define N_NODES 100000
#define N_EDGES 20000
#define NNZ     1600000
#define LDA1    304     // padded fp16 row stride for K=300 (16B-aligned rows)

// ---------------- scratch (device globals; zero-initialized at module load) ----------
// RULE: each array is accessed EITHER only via host-passed args OR only via device
// symbols — never both (host/device symbol resolutions differ on this toolchain).
__device__ __half          g_bufA[(size_t)N_EDGES * LDA1]; // eagg per layer (host-arg only) 12.2MB
__device__ __half          g_bufB[(size_t)N_EDGES * 256];  // ew per layer (host-arg only) 10.2MB
__device__ int             g_ecnt[N_EDGES];                // degrees (device-symbol only)
__device__ int             g_ncnt[N_NODES];
__device__ int             g_estart[N_EDGES];              // CSR offsets (device-symbol only)
__device__ int             g_nstart[N_NODES];
__device__ int             g_ecur[N_EDGES];                // scatter cursors (device-symbol only)
__device__ int             g_ncur[N_NODES];
__device__ int             g_eitems[NNZ];                  // per-edge node lists (6.4MB)
__device__ unsigned short  g_nitems[NNZ];                  // per-node edge lists (3.2MB)
__device__ float           g_logits[N_NODES];
__device__ float           g_partmax[12500];
__device__ float           g_gmax;
__device__ float           g_acc[129];                     // [0..127] sum, [128]=Z

static __device__ __forceinline__ void acc_h4(float4& acc, uint2 raw) {
    float2 f0 = __half22float2(*reinterpret_cast<__half2*>(&raw.x));
    float2 f1 = __half22float2(*reinterpret_cast<__half2*>(&raw.y));
    acc.x += f0.x; acc.y += f0.y; acc.z += f1.x; acc.w += f1.y;
}
static __device__ __forceinline__ uint2 pack_h4(float4 o) {
    __half2 v0 = __floats2half2_rn(o.x, o.y);
    __half2 v1 = __floats2half2_rn(o.z, o.w);
    uint2 pk;
    pk.x = *reinterpret_cast<unsigned*>(&v0);
    pk.y = *reinterpret_cast<unsigned*>(&v1);
    return pk;
}

// ---------------- zero degree arrays (start of every call) ---------------------------
__global__ void zero_kernel() {
    int i = blockIdx.x * blockDim.x + threadIdx.x;
    int stride = gridDim.x * blockDim.x;
    for (int j = i; j < N_EDGES; j += stride) g_ecnt[j] = 0;
    for (int j = i; j < N_NODES; j += stride) g_ncnt[j] = 0;
}

// ---------------- degree histogram ---------------------------------------------------
__global__ void hist_kernel(const int* __restrict__ nidx, const int* __restrict__ eidx) {
    int i = blockIdx.x * blockDim.x + threadIdx.x;
    int stride = gridDim.x * blockDim.x;
    for (int j = i; j < NNZ; j += stride) {
        atomicAdd(&g_ecnt[eidx[j]], 1);
        atomicAdd(&g_ncnt[nidx[j]], 1);
    }
}

// ---------------- exclusive scan: block 0 -> edges, block 1 -> nodes -----------------
__global__ void scan_kernel() {
    const bool edges = (blockIdx.x == 0);
    int*       cnt    = edges ? g_ecnt   : g_ncnt;
    int*       start  = edges ? g_estart : g_nstart;
    int*       cursor = edges ? g_ecur   : g_ncur;
    const int  n      = edges ? N_EDGES  : N_NODES;

    __shared__ int sh[1024];
    __shared__ int s_carry;
    if (threadIdx.x == 0) s_carry = 0;
    __syncthreads();
    for (int base = 0; base < n; base += 1024) {
        int i = base + threadIdx.x;
        int v = (i < n) ? cnt[i] : 0;
        sh[threadIdx.x] = v;
        __syncthreads();
        for (int off = 1; off < 1024; off <<= 1) {
            int t = 0;
            if (threadIdx.x >= off) t = sh[threadIdx.x - off];
            __syncthreads();
            if (threadIdx.x >= off) sh[threadIdx.x] += t;
            __syncthreads();
        }
        int carry = s_carry;
        int incl = sh[threadIdx.x];
        if (i < n) {
            int excl = carry + incl - v;
            start[i] = excl;
            cursor[i] = excl;
        }
        __syncthreads();
        if (threadIdx.x == 1023) s_carry = carry + sh[1023];
        __syncthreads();
    }
}

// ---------------- CSR scatter --------------------------------------------------------
__global__ void scatter_kernel(const int* __restrict__ nidx, const int* __restrict__ eidx) {
    int i = blockIdx.x * blockDim.x + threadIdx.x;
    int stride = gridDim.x * blockDim.x;
    for (int j = i; j < NNZ; j += stride) {
        int n = nidx[j];
        int e = eidx[j];
        int p = atomicAdd(&g_ecur[e], 1);
        g_eitems[p] = n;
        int q = atomicAdd(&g_ncur[n], 1);
        g_nitems[q] = (unsigned short)e;
    }
}

// ---------------- layer-1 edge aggregation: fp32 x -> fp16 eagg1 (stride LDA1) -------
// warp per (edge, 128-feature chunk); 8 independent float4 gathers in flight.
// Also zeroes pad columns [F, LDOUT) so the GEMM can read them safely.
template <int F, int CHUNKS, int LDOUT>
__global__ __launch_bounds__(256) void agg_edge_x(const float* __restrict__ src,
                                                  __half* __restrict__ dst) {
    int w = (blockIdx.x * blockDim.x + threadIdx.x) >> 5;
    int lane = threadIdx.x & 31;
    int row = w / CHUNKS;
    int ch  = w % CHUNKS;
    if (row >= N_EDGES) return;

    const int* __restrict__ lst = g_eitems + g_estart[row];
    int cnt = g_ecnt[row];

    int colbase = ch * 128 + lane * 4;
    const bool active = colbase < F;
    const float* __restrict__ sp = src + colbase;

    float4 acc = make_float4(0.f, 0.f, 0.f, 0.f);
    int i = 0;
    for (; i + 8 <= cnt; i += 8) {
        int idxreg = 0;
        if (lane < 8) idxreg = lst[i + lane];
        int ns[8];
#pragma unroll
        for (int k = 0; k < 8; k++) ns[k] = __shfl_sync(0xffffffffu, idxreg, k);
        float4 t[8];
#pragma unroll
        for (int k = 0; k < 8; k++) {
            t[k] = make_float4(0.f, 0.f, 0.f, 0.f);
            if (active) t[k] = *(const float4*)(sp + (size_t)ns[k] * F);
        }
#pragma unroll
        for (int k = 0; k < 8; k++) {
            acc.x += t[k].x; acc.y += t[k].y; acc.z += t[k].z; acc.w += t[k].w;
        }
    }
    for (; i < cnt; i++) {
        if (active) {
            float4 t = *(const float4*)(sp + (size_t)lst[i] * F);
            acc.x += t.x; acc.y += t.y; acc.z += t.z; acc.w += t.w;
        }
    }
    if (active) {
        float inv = (cnt > 0) ? 1.0f / (float)cnt : 0.0f;
        float4 o = make_float4(acc.x * inv, acc.y * inv, acc.z * inv, acc.w * inv);
        *(uint2*)(dst + (size_t)row * LDOUT + colbase) = pack_h4(o);
    } else if (colbase < LDOUT) {
        *(uint2*)(dst + (size_t)row * LDOUT + colbase) = make_uint2(0u, 0u);  // pad = 0
    }
}

// ---------------- double-gather edge aggregation (layers 2-3) ------------------------
// eagg[e] = mean_{n in e} lrelu( bias + mean_{e' in n} ew[e'] )  — h never materialized.
// ew rows have FEW=256 cols; warp per (edge, 128-feat chunk); fp32 inner math.
__global__ __launch_bounds__(256) void agg_edge_dg(const __half* __restrict__ ew,
                                                   __half* __restrict__ dst,
                                                   const float* __restrict__ bias) {
    int w = (blockIdx.x * blockDim.x + threadIdx.x) >> 5;
    int lane = threadIdx.x & 31;
    int row = w >> 1;            // edge id (2 chunks)
    int ch  = w & 1;
    if (row >= N_EDGES) return;

    const int* __restrict__ lst = g_eitems + g_estart[row];
    int cnt = g_ecnt[row];

    int colbase = ch * 128 + lane * 4;
    const __half* __restrict__ sp = ew + colbase;
    float4 bb = *(const float4*)(bias + colbase);

    float4 acc = make_float4(0.f, 0.f, 0.f, 0.f);
    for (int i = 0; i < cnt; i += 8) {
        int m = cnt - i; if (m > 8) m = 8;
        int nid = 0, sn = 0, cn = 0;
        if (lane < m) {
            nid = lst[i + lane];
            sn = g_nstart[nid];
            cn = g_ncnt[nid];
        }
        for (int k = 0; k < m; k++) {
            int snk = __shfl_sync(0xffffffffu, sn, k);
            int cnk = __shfl_sync(0xffffffffu, cn, k);
            float4 inner = make_float4(0.f, 0.f, 0.f, 0.f);
            for (int j = 0; j < cnk; j += 8) {
                int rem = cnk - j; if (rem > 8) rem = 8;
                int er = 0;
                if (lane < rem) er = (int)g_nitems[snk + j + lane];
                int es[8];
#pragma unroll
                for (int t = 0; t < 8; t++) es[t] = __shfl_sync(0xffffffffu, er, t);
                uint2 raw[8];
#pragma unroll
                for (int t = 0; t < 8; t++) {
                    raw[t] = make_uint2(0u, 0u);
                    if (t < rem) raw[t] = *(const uint2*)(sp + (size_t)es[t] * 256);
                }
#pragma unroll
                for (int t = 0; t < 8; t++) acc_h4(inner, raw[t]);
            }
            float innv = (cnk > 0) ? 1.0f / (float)cnk : 0.0f;
            float4 h;
            h.x = inner.x * innv + bb.x;
            h.y = inner.y * innv + bb.y;
            h.z = inner.z * innv + bb.z;
            h.w = inner.w * innv + bb.w;
            h.x = (h.x > 0.f) ? h.x : 0.01f * h.x;
            h.y = (h.y > 0.f) ? h.y : 0.01f * h.y;
            h.z = (h.z > 0.f) ? h.z : 0.01f * h.z;
            h.w = (h.w > 0.f) ? h.w : 0.01f * h.w;
            acc.x += h.x; acc.y += h.y; acc.z += h.z; acc.w += h.w;
        }
    }
    float inv = (cnt > 0) ? 1.0f / (float)cnt : 0.0f;
    float4 o = make_float4(acc.x * inv, acc.y * inv, acc.z * inv, acc.w * inv);
    *(uint2*)(dst + (size_t)row * 256 + colbase) = pack_h4(o);
}

// ---------------- SGEMM: fp16 A (lda-padded), fp32 B, fp16 C, fp32 accum -------------
// BM=128, BN=64, BK=16, 256 threads, 8x4 per thread. A pads must be zero.
__global__ __launch_bounds__(256) void sgemm_kernel(const __half* __restrict__ A,
                                                    const float* __restrict__ B,
                                                    __half* __restrict__ C,
                                                    int M, int K, int N, int lda) {
    __shared__ float As[16][136];
    __shared__ float Bs[16][64];
    const int tid = threadIdx.x;
    const int bm = blockIdx.x * 128;
    const int bn = blockIdx.y * 64;
    const int a_row = tid >> 1;
    const int a_grp = (tid & 1) * 8;
    const int b_row = tid >> 4;
    const int b_col = (tid & 15) * 4;
    const int ty = tid >> 4;
    const int tx = tid & 15;
    float acc[8][4];
#pragma unroll
    for (int i = 0; i < 8; i++)
#pragma unroll
        for (int j = 0; j < 4; j++) acc[i][j] = 0.f;

    const bool arow_ok = (bm + a_row) < M;
    const __half* Ab = A + (size_t)(bm + a_row) * lda;

    for (int kt = 0; kt < K; kt += 16) {
        {
            uint4 raw = make_uint4(0u, 0u, 0u, 0u);
            if (arow_ok) raw = *(const uint4*)(Ab + kt + a_grp);
            const __half2* hp = reinterpret_cast<const __half2*>(&raw);
#pragma unroll
            for (int j = 0; j < 4; j++) {
                float2 f = __half22float2(hp[j]);
                As[a_grp + j * 2 + 0][a_row] = f.x;
                As[a_grp + j * 2 + 1][a_row] = f.y;
            }
        }
        {
            int k = kt + b_row;
            float4 bv = make_float4(0.f, 0.f, 0.f, 0.f);
            if (k < K) bv = *(const float4*)(B + (size_t)k * N + bn + b_col);
            *(float4*)&Bs[b_row][b_col] = bv;
        }
        __syncthreads();
#pragma unroll
        for (int k = 0; k < 16; k++) {
            float4 a0 = *(const float4*)&As[k][ty * 8];
            float4 a1 = *(const float4*)&As[k][ty * 8 + 4];
            float4 bv = *(const float4*)&Bs[k][tx * 4];
            float a[8] = {a0.x, a0.y, a0.z, a0.w, a1.x, a1.y, a1.z, a1.w};
            float b[4] = {bv.x, bv.y, bv.z, bv.w};
#pragma unroll
            for (int i = 0; i < 8; i++)
#pragma unroll
                for (int j = 0; j < 4; j++) acc[i][j] += a[i] * b[j];
        }
        __syncthreads();
    }
#pragma unroll
    for (int i = 0; i < 8; i++) {
        int r = bm + ty * 8 + i;
        if (r < M) {
            float4 o = make_float4(acc[i][0], acc[i][1], acc[i][2], acc[i][3]);
            *(uint2*)(C + (size_t)r * N + bn + tx * 4) = pack_h4(o);
        }
    }
}

// ---------------- h3 recompute helper: mean of node's ew3 rows + b3 ------------------
static __device__ __forceinline__ float4 node_h3(const __half* __restrict__ ew3,
                                                 const float* __restrict__ b3,
                                                 int node, int lane) {
    int s = g_nstart[node], cn = g_ncnt[node];
    const __half* sp = ew3 + lane * 4;
    float4 acc = make_float4(0.f, 0.f, 0.f, 0.f);
    for (int j = 0; j < cn; j += 8) {
        int rem = cn - j; if (rem > 8) rem = 8;
        int er = 0;
        if (lane < rem) er = (int)g_nitems[s + j + lane];
        int es[8];
#pragma unroll
        for (int t = 0; t < 8; t++) es[t] = __shfl_sync(0xffffffffu, er, t);
        uint2 raw[8];
#pragma unroll
        for (int t = 0; t < 8; t++) {
            raw[t] = make_uint2(0u, 0u);
            if (t < rem) raw[t] = *(const uint2*)(sp + (size_t)es[t] * 128);
        }
#pragma unroll
        for (int t = 0; t < 8; t++) acc_h4(acc, raw[t]);
    }
    float inv = (cn > 0) ? 1.0f / (float)cn : 0.0f;
    float4 bb = *(const float4*)(b3 + lane * 4);
    return make_float4(acc.x * inv + bb.x, acc.y * inv + bb.y,
                       acc.z * inv + bb.z, acc.w * inv + bb.w);
}

// ---------------- logits pass: warp per node, h3 on the fly --------------------------
__global__ __launch_bounds__(256) void logits_kernel(const __half* __restrict__ ew3,
                                                     const float* __restrict__ b3,
                                                     const float* __restrict__ aw,
                                                     const float* __restrict__ ab) {
    __shared__ float smax[8];
    int gw = (blockIdx.x * blockDim.x + threadIdx.x) >> 5;   // node
    int lane = threadIdx.x & 31;
    float lg = -1e30f;
    if (gw < N_NODES) {
        float4 h = node_h3(ew3, b3, gw, lane);
        float4 wv = ((const float4*)aw)[lane];
        float d = h.x * wv.x + h.y * wv.y + h.z * wv.z + h.w * wv.w;
#pragma unroll
        for (int off = 16; off > 0; off >>= 1) d += __shfl_xor_sync(0xffffffffu, d, off);
        d += ab[0];
        if (lane == 0) g_logits[gw] = d;
        lg = d;
    }
    int wl = threadIdx.x >> 5;
    if (lane == 0) smax[wl] = lg;
    __syncthreads();
    if (threadIdx.x == 0) {
        float m = smax[0];
#pragma unroll
        for (int j = 1; j < 8; j++) m = fmaxf(m, smax[j]);
        g_partmax[blockIdx.x] = m;
    }
}

__global__ void maxred_kernel(int nparts) {
    __shared__ float sm[32];
    if (threadIdx.x < 129) g_acc[threadIdx.x] = 0.0f;
    float m = -1e30f;
    for (int i = threadIdx.x; i < nparts; i += 1024) m = fmaxf(m, g_partmax[i]);
#pragma unroll
    for (int off = 16; off > 0; off >>= 1) m = fmaxf(m, __shfl_xor_sync(0xffffffffu, m, off));
    if ((threadIdx.x & 31) == 0) sm[threadIdx.x >> 5] = m;
    __syncthreads();
    if (threadIdx.x < 32) {
        float v = sm[threadIdx.x];
#pragma unroll
        for (int off = 16; off > 0; off >>= 1) v = fmaxf(v, __shfl_xor_sync(0xffffffffu, v, off));
        if (threadIdx.x == 0) g_gmax = v;
    }
}

// ---------------- accumulate pass: warp per node, block-reduce, atomic ---------------
__global__ __launch_bounds__(256) void accum_kernel(const __half* __restrict__ ew3,
                                                    const float* __restrict__ b3) {
    __shared__ float sred[8][128];
    __shared__ float sz[8];
    int wl = threadIdx.x >> 5;
    int lane = threadIdx.x & 31;
    int gw = (blockIdx.x * blockDim.x + threadIdx.x) >> 5;   // node
    float gmax = g_gmax;
    float4 wacc = make_float4(0.f, 0.f, 0.f, 0.f);
    float z = 0.f;
    if (gw < N_NODES) {
        float4 h = node_h3(ew3, b3, gw, lane);
        float wgt = expf(g_logits[gw] - gmax);
        wacc.x = wgt * h.x; wacc.y = wgt * h.y; wacc.z = wgt * h.z; wacc.w = wgt * h.w;
        z = wgt;
    }
    *(float4*)&sred[wl][lane * 4] = wacc;
    if (lane == 0) sz[wl] = z;
    __syncthreads();
    if (threadIdx.x < 128) {
        float s = 0.f;
#pragma unroll
        for (int j = 0; j < 8; j++) s += sred[j][threadIdx.x];
        atomicAdd(&g_acc[threadIdx.x], s);
    } else if (threadIdx.x == 128) {
        float s = 0.f;
#pragma unroll
        for (int j = 0; j < 8; j++) s += sz[j];
        atomicAdd(&g_acc[128], s);
    }
}

__global__ void finalize_kernel(float* __restrict__ out) {
    int t = threadIdx.x;
    out[t] = g_acc[t] / g_acc[128];
}

// ---------------- launch -------------------------------------------------------------
extern "C" void kernel_launch(void* const* d_in, const int* in_sizes, int n_in,
                              void* d_out, int out_size) {
    const float* x       = (const float*)d_in[0];          // [100000, 300]
    const int*   nidx    = (const int*)d_in[1];
    const int*   eidx    = ((const int*)d_in[1]) + NNZ;
    const float* W1      = (const float*)d_in[2];          // [300,256]
    const float* b1      = (const float*)d_in[3];
    const float* W2      = (const float*)d_in[4];          // [256,256]
    const float* b2      = (const float*)d_in[5];
    const float* W3      = (const float*)d_in[6];          // [256,128]
    const float* b3      = (const float*)d_in[7];
    const float* attn_W  = (const float*)d_in[8];          // [128,1]
    const float* attn_b  = (const float*)d_in[9];          // [1]
    float* out = (float*)d_out;                            // [128]

    // CSR build (slot 4 = scatter for ncu capture)
    zero_kernel<<<512, 256>>>();
    hist_kernel<<<2048, 256>>>(nidx, eidx);
    scan_kernel<<<2, 1024>>>();
    scatter_kernel<<<2048, 256>>>(nidx, eidx);             // <- capture

    // Layer 1: eagg1 = mean x over members (bufA, lda 304); ew1 = eagg1@W1 (bufB)
    agg_edge_x<300, 3, LDA1><<<7500, 256>>>(x, g_bufA);
    sgemm_kernel<<<dim3(157, 4), 256>>>(g_bufA, W1, g_bufB, N_EDGES, 300, 256, LDA1);

    // Layer 2: eagg2 via double-gather over ew1 (bufB->bufA); ew2 = eagg2@W2 (bufA->bufB)
    agg_edge_dg<<<5000, 256>>>(g_bufB, g_bufA, b1);
    sgemm_kernel<<<dim3(157, 4), 256>>>(g_bufA, W2, g_bufB, N_EDGES, 256, 256, 256);

    // Layer 3: eagg3 via double-gather over ew2; ew3 = eagg3@W3 (N=128)
    agg_edge_dg<<<5000, 256>>>(g_bufB, g_bufA, b2);
    sgemm_kernel<<<dim3(157, 2), 256>>>(g_bufA, W3, g_bufB, N_EDGES, 256, 128, 256);

    // Attention pooling: h3 recomputed on the fly from ew3 (bufB, stride 128)
    logits_kernel<<<12500, 256>>>(g_bufB, b3, attn_W, attn_b);
    maxred_kernel<<<1, 1024>>>(12500);
    accum_kernel<<<12500, 256>>>(g_bufB, b3);
    finalize_kernel<<<1, 128>>>(out);
}

// round 14
// speedup vs baseline: 4.1504x; 4.1504x over previous
#include <cuda_runtime.h>
#include <cuda_fp16.h>

#define N_NODES 100000
#define N_EDGES 20000
#define NNZ     1600000
#define LDA1    304     // padded fp32 row stride for K=300 (16B-aligned float4 rows)

// ---------------- scratch (device globals; zero-initialized at module load) ----------
// RULE: each array is accessed EITHER only via host-passed args OR only via device
// symbols — never both (host/device symbol resolutions differ on this toolchain).
__device__ float           g_eagg[(size_t)N_EDGES * LDA1]; // fp32 edge-agg / scatter target (24.3MB, host-arg only)
__device__ __half          g_ew[(size_t)N_EDGES * 256];    // edge feats after W (10.2MB, host-arg only)
__device__ int             g_ecnt[N_EDGES];                // degrees (device-symbol only; zeroed by finalize)
__device__ int             g_ncnt[N_NODES];
__device__ int             g_estart[N_EDGES];              // CSR offsets (device-symbol only)
__device__ int             g_nstart[N_NODES];
__device__ int             g_ecur[N_EDGES];                // scatter cursors (device-symbol only)
__device__ int             g_ncur[N_NODES];
__device__ int             g_eitems[NNZ];                  // per-edge node lists (6.4MB)
__device__ unsigned short  g_nitems[NNZ];                  // per-node edge lists (3.2MB)
__device__ float           g_logits[N_NODES];
__device__ float           g_partmax[12500];
__device__ float           g_gmax;
__device__ float           g_acc[129];                     // [0..127] sum, [128]=Z

static __device__ __forceinline__ void acc_h4(float4& acc, uint2 raw) {
    float2 f0 = __half22float2(*reinterpret_cast<__half2*>(&raw.x));
    float2 f1 = __half22float2(*reinterpret_cast<__half2*>(&raw.y));
    acc.x += f0.x; acc.y += f0.y; acc.z += f1.x; acc.w += f1.y;
}
static __device__ __forceinline__ uint2 pack_h4(float4 o) {
    __half2 v0 = __floats2half2_rn(o.x, o.y);
    __half2 v1 = __floats2half2_rn(o.z, o.w);
    uint2 pk;
    pk.x = *reinterpret_cast<unsigned*>(&v0);
    pk.y = *reinterpret_cast<unsigned*>(&v1);
    return pk;
}

// gather-mean of a node's ew rows (stride STRIDE), fp32 accum, MLP=8
template <int STRIDE>
static __device__ __forceinline__ float4 node_gather(const __half* __restrict__ ew,
                                                     int s, int cn, int colbase, int lane) {
    const __half* sp = ew + colbase;
    float4 acc = make_float4(0.f, 0.f, 0.f, 0.f);
    for (int j = 0; j < cn; j += 8) {
        int rem = cn - j; if (rem > 8) rem = 8;
        int er = 0;
        if (lane < rem) er = (int)g_nitems[s + j + lane];
        int es[8];
#pragma unroll
        for (int t = 0; t < 8; t++) es[t] = __shfl_sync(0xffffffffu, er, t);
        uint2 raw[8];
#pragma unroll
        for (int t = 0; t < 8; t++) {
            raw[t] = make_uint2(0u, 0u);
            if (t < rem) raw[t] = *(const uint2*)(sp + (size_t)es[t] * STRIDE);
        }
#pragma unroll
        for (int t = 0; t < 8; t++) acc_h4(acc, raw[t]);
    }
    return acc;
}

// ---------------- degree histogram (cnt zero at entry: static init / finalize) -------
__global__ void hist_kernel(const int* __restrict__ nidx, const int* __restrict__ eidx) {
    int i = blockIdx.x * blockDim.x + threadIdx.x;
    int stride = gridDim.x * blockDim.x;
    for (int j = i; j < NNZ; j += stride) {
        atomicAdd(&g_ecnt[eidx[j]], 1);
        atomicAdd(&g_ncnt[nidx[j]], 1);
    }
}

// ---------------- exclusive scan: block 0 -> edges, block 1 -> nodes -----------------
__global__ void scan_kernel() {
    const bool edges = (blockIdx.x == 0);
    int*       cnt    = edges ? g_ecnt   : g_ncnt;
    int*       start  = edges ? g_estart : g_nstart;
    int*       cursor = edges ? g_ecur   : g_ncur;
    const int  n      = edges ? N_EDGES  : N_NODES;

    __shared__ int sh[1024];
    __shared__ int s_carry;
    if (threadIdx.x == 0) s_carry = 0;
    __syncthreads();
    for (int base = 0; base < n; base += 1024) {
        int i = base + threadIdx.x;
        int v = (i < n) ? cnt[i] : 0;
        sh[threadIdx.x] = v;
        __syncthreads();
        for (int off = 1; off < 1024; off <<= 1) {
            int t = 0;
            if (threadIdx.x >= off) t = sh[threadIdx.x - off];
            __syncthreads();
            if (threadIdx.x >= off) sh[threadIdx.x] += t;
            __syncthreads();
        }
        int carry = s_carry;
        int incl = sh[threadIdx.x];
        if (i < n) {
            int excl = carry + incl - v;
            start[i] = excl;
            cursor[i] = excl;
        }
        __syncthreads();
        if (threadIdx.x == 1023) s_carry = carry + sh[1023];
        __syncthreads();
    }
}

// ---------------- CSR scatter --------------------------------------------------------
__global__ void csr_kernel(const int* __restrict__ nidx, const int* __restrict__ eidx) {
    int i = blockIdx.x * blockDim.x + threadIdx.x;
    int stride = gridDim.x * blockDim.x;
    for (int j = i; j < NNZ; j += stride) {
        int n = nidx[j];
        int e = eidx[j];
        int p = atomicAdd(&g_ecur[e], 1);
        g_eitems[p] = n;
        int q = atomicAdd(&g_ncur[n], 1);
        g_nitems[q] = (unsigned short)e;
    }
}

// ---------------- layer-1 edge aggregation: fp32 x -> fp32 eagg1 (stride LDA1) -------
// warp per (edge, 128-col chunk); 8 independent float4 gathers; zeroes pad cols.
__global__ __launch_bounds__(256) void agg_edge_x(const float* __restrict__ src,
                                                  float* __restrict__ dst) {
    const int F = 300, CHUNKS = 3;
    int w = (blockIdx.x * blockDim.x + threadIdx.x) >> 5;
    int lane = threadIdx.x & 31;
    int row = w / CHUNKS;
    int ch  = w % CHUNKS;
    if (row >= N_EDGES) return;

    const int* __restrict__ lst = g_eitems + g_estart[row];
    int cnt = g_ecnt[row];

    int colbase = ch * 128 + lane * 4;
    const bool active = colbase < F;
    const float* __restrict__ sp = src + colbase;

    float4 acc = make_float4(0.f, 0.f, 0.f, 0.f);
    int i = 0;
    for (; i + 8 <= cnt; i += 8) {
        int idxreg = 0;
        if (lane < 8) idxreg = lst[i + lane];
        int ns[8];
#pragma unroll
        for (int k = 0; k < 8; k++) ns[k] = __shfl_sync(0xffffffffu, idxreg, k);
        float4 t[8];
#pragma unroll
        for (int k = 0; k < 8; k++) {
            t[k] = make_float4(0.f, 0.f, 0.f, 0.f);
            if (active) t[k] = *(const float4*)(sp + (size_t)ns[k] * F);
        }
#pragma unroll
        for (int k = 0; k < 8; k++) {
            acc.x += t[k].x; acc.y += t[k].y; acc.z += t[k].z; acc.w += t[k].w;
        }
    }
    for (; i < cnt; i++) {
        if (active) {
            float4 t = *(const float4*)(sp + (size_t)lst[i] * F);
            acc.x += t.x; acc.y += t.y; acc.z += t.z; acc.w += t.w;
        }
    }
    if (active) {
        float inv = (cnt > 0) ? 1.0f / (float)cnt : 0.0f;
        *(float4*)(dst + (size_t)row * LDA1 + colbase) =
            make_float4(acc.x * inv, acc.y * inv, acc.z * inv, acc.w * inv);
    } else if (colbase < LDA1) {
        *(float4*)(dst + (size_t)row * LDA1 + colbase) = make_float4(0.f, 0.f, 0.f, 0.f);
    }
}

// ---------------- zero the 256-stride eagg region before a scatter pass --------------
__global__ void zero_eagg_kernel(float* __restrict__ eagg) {
    const int total4 = N_EDGES * 256 / 4;
    int i = blockIdx.x * blockDim.x + threadIdx.x;
    int stride = gridDim.x * blockDim.x;
    for (int j = i; j < total4; j += stride)
        ((float4*)eagg)[j] = make_float4(0.f, 0.f, 0.f, 0.f);
}

// ---------------- fused node-compute + scatter (layers 2-3) --------------------------
// warp per (node, chunk): h_n = lrelu(bias + mean of its ew rows), then
// atomicAdd h_n/cnt_e into eagg[e] for each incident edge e. h never stored.
__global__ __launch_bounds__(256) void fuse_scatter_kernel(const __half* __restrict__ ew,
                                                           float* __restrict__ eagg,
                                                           const float* __restrict__ bias) {
    int w = (blockIdx.x * blockDim.x + threadIdx.x) >> 5;
    int lane = threadIdx.x & 31;
    int node = w >> 1;
    int ch   = w & 1;
    if (node >= N_NODES) return;
    int s = g_nstart[node], cn = g_ncnt[node];
    if (cn == 0) return;                       // isolated node contributes nothing

    int colbase = ch * 128 + lane * 4;
    float4 acc = node_gather<256>(ew, s, cn, colbase, lane);
    float inv = 1.0f / (float)cn;
    float4 bb = *(const float4*)(bias + colbase);
    float4 h;
    h.x = acc.x * inv + bb.x;
    h.y = acc.y * inv + bb.y;
    h.z = acc.z * inv + bb.z;
    h.w = acc.w * inv + bb.w;
    h.x = (h.x > 0.f) ? h.x : 0.01f * h.x;
    h.y = (h.y > 0.f) ? h.y : 0.01f * h.y;
    h.z = (h.z > 0.f) ? h.z : 0.01f * h.z;
    h.w = (h.w > 0.f) ? h.w : 0.01f * h.w;

    for (int i = 0; i < cn; i++) {
        int e = (int)g_nitems[s + i];                    // broadcast load
        float invc = 1.0f / (float)g_ecnt[e];
        float4 v = make_float4(h.x * invc, h.y * invc, h.z * invc, h.w * invc);
        atomicAdd((float4*)(eagg + (size_t)e * 256 + colbase), v);
    }
}

// ---------------- SGEMM: fp32 A (lda-padded), fp32 B, fp16 C, fp32 accum -------------
// BM=128, BN=64, BK=16, 256 threads, 8x4 per thread. A pad cols must be zero.
__global__ __launch_bounds__(256) void sgemm_kernel(const float* __restrict__ A,
                                                    const float* __restrict__ B,
                                                    __half* __restrict__ C,
                                                    int M, int K, int N, int lda) {
    __shared__ float As[16][136];
    __shared__ float Bs[16][64];
    const int tid = threadIdx.x;
    const int bm = blockIdx.x * 128;
    const int bn = blockIdx.y * 64;
    const int a_row = tid >> 1;            // 0..127
    const int a_grp = (tid & 1) * 8;       // 0 or 8
    const int b_row = tid >> 4;            // 0..15
    const int b_col = (tid & 15) * 4;      // 0..60
    const int ty = tid >> 4;
    const int tx = tid & 15;
    float acc[8][4];
#pragma unroll
    for (int i = 0; i < 8; i++)
#pragma unroll
        for (int j = 0; j < 4; j++) acc[i][j] = 0.f;

    const bool arow_ok = (bm + a_row) < M;
    const float* Ab = A + (size_t)(bm + a_row) * lda;

    for (int kt = 0; kt < K; kt += 16) {
        {   // A: 8 floats = 2 float4 (pads beyond K are zero in the buffer)
            float4 r0 = make_float4(0.f, 0.f, 0.f, 0.f);
            float4 r1 = make_float4(0.f, 0.f, 0.f, 0.f);
            if (arow_ok) {
                r0 = *(const float4*)(Ab + kt + a_grp);
                r1 = *(const float4*)(Ab + kt + a_grp + 4);
            }
            As[a_grp + 0][a_row] = r0.x; As[a_grp + 1][a_row] = r0.y;
            As[a_grp + 2][a_row] = r0.z; As[a_grp + 3][a_row] = r0.w;
            As[a_grp + 4][a_row] = r1.x; As[a_grp + 5][a_row] = r1.y;
            As[a_grp + 6][a_row] = r1.z; As[a_grp + 7][a_row] = r1.w;
        }
        {   // B
            int k = kt + b_row;
            float4 bv = make_float4(0.f, 0.f, 0.f, 0.f);
            if (k < K) bv = *(const float4*)(B + (size_t)k * N + bn + b_col);
            *(float4*)&Bs[b_row][b_col] = bv;
        }
        __syncthreads();
#pragma unroll
        for (int k = 0; k < 16; k++) {
            float4 a0 = *(const float4*)&As[k][ty * 8];
            float4 a1 = *(const float4*)&As[k][ty * 8 + 4];
            float4 bv = *(const float4*)&Bs[k][tx * 4];
            float a[8] = {a0.x, a0.y, a0.z, a0.w, a1.x, a1.y, a1.z, a1.w};
            float b[4] = {bv.x, bv.y, bv.z, bv.w};
#pragma unroll
            for (int i = 0; i < 8; i++)
#pragma unroll
                for (int j = 0; j < 4; j++) acc[i][j] += a[i] * b[j];
        }
        __syncthreads();
    }
#pragma unroll
    for (int i = 0; i < 8; i++) {
        int r = bm + ty * 8 + i;
        if (r < M) {
            float4 o = make_float4(acc[i][0], acc[i][1], acc[i][2], acc[i][3]);
            *(uint2*)(C + (size_t)r * N + bn + tx * 4) = pack_h4(o);
        }
    }
}

// ---------------- h3 on the fly: mean of node's ew3 rows (stride 128) + b3 -----------
static __device__ __forceinline__ float4 node_h3(const __half* __restrict__ ew3,
                                                 const float* __restrict__ b3,
                                                 int node, int lane) {
    int s = g_nstart[node], cn = g_ncnt[node];
    float4 acc = node_gather<128>(ew3, s, cn, lane * 4, lane);
    float inv = (cn > 0) ? 1.0f / (float)cn : 0.0f;
    float4 bb = *(const float4*)(b3 + lane * 4);
    return make_float4(acc.x * inv + bb.x, acc.y * inv + bb.y,
                       acc.z * inv + bb.z, acc.w * inv + bb.w);
}

// ---------------- logits pass: warp per node ----------------------------------------
__global__ __launch_bounds__(256) void logits_kernel(const __half* __restrict__ ew3,
                                                     const float* __restrict__ b3,
                                                     const float* __restrict__ aw,
                                                     const float* __restrict__ ab) {
    __shared__ float smax[8];
    int gw = (blockIdx.x * blockDim.x + threadIdx.x) >> 5;
    int lane = threadIdx.x & 31;
    float lg = -1e30f;
    if (gw < N_NODES) {
        float4 h = node_h3(ew3, b3, gw, lane);
        float4 wv = ((const float4*)aw)[lane];
        float d = h.x * wv.x + h.y * wv.y + h.z * wv.z + h.w * wv.w;
#pragma unroll
        for (int off = 16; off > 0; off >>= 1) d += __shfl_xor_sync(0xffffffffu, d, off);
        d += ab[0];
        if (lane == 0) g_logits[gw] = d;
        lg = d;
    }
    int wl = threadIdx.x >> 5;
    if (lane == 0) smax[wl] = lg;
    __syncthreads();
    if (threadIdx.x == 0) {
        float m = smax[0];
#pragma unroll
        for (int j = 1; j < 8; j++) m = fmaxf(m, smax[j]);
        g_partmax[blockIdx.x] = m;
    }
}

__global__ void maxred_kernel(int nparts) {
    __shared__ float sm[32];
    if (threadIdx.x < 129) g_acc[threadIdx.x] = 0.0f;
    float m = -1e30f;
    for (int i = threadIdx.x; i < nparts; i += 1024) m = fmaxf(m, g_partmax[i]);
#pragma unroll
    for (int off = 16; off > 0; off >>= 1) m = fmaxf(m, __shfl_xor_sync(0xffffffffu, m, off));
    if ((threadIdx.x & 31) == 0) sm[threadIdx.x >> 5] = m;
    __syncthreads();
    if (threadIdx.x < 32) {
        float v = sm[threadIdx.x];
#pragma unroll
        for (int off = 16; off > 0; off >>= 1) v = fmaxf(v, __shfl_xor_sync(0xffffffffu, v, off));
        if (threadIdx.x == 0) g_gmax = v;
    }
}

// ---------------- accumulate pass: warp per node, block-reduce, atomic ---------------
__global__ __launch_bounds__(256) void accum_kernel(const __half* __restrict__ ew3,
                                                    const float* __restrict__ b3) {
    __shared__ float sred[8][128];
    __shared__ float sz[8];
    int wl = threadIdx.x >> 5;
    int lane = threadIdx.x & 31;
    int gw = (blockIdx.x * blockDim.x + threadIdx.x) >> 5;
    float gmax = g_gmax;
    float4 wacc = make_float4(0.f, 0.f, 0.f, 0.f);
    float z = 0.f;
    if (gw < N_NODES) {
        float4 h = node_h3(ew3, b3, gw, lane);
        float wgt = expf(g_logits[gw] - gmax);
        wacc.x = wgt * h.x; wacc.y = wgt * h.y; wacc.z = wgt * h.z; wacc.w = wgt * h.w;
        z = wgt;
    }
    *(float4*)&sred[wl][lane * 4] = wacc;
    if (lane == 0) sz[wl] = z;
    __syncthreads();
    if (threadIdx.x < 128) {
        float s = 0.f;
#pragma unroll
        for (int j = 0; j < 8; j++) s += sred[j][threadIdx.x];
        atomicAdd(&g_acc[threadIdx.x], s);
    } else if (threadIdx.x == 128) {
        float s = 0.f;
#pragma unroll
        for (int j = 0; j < 8; j++) s += sz[j];
        atomicAdd(&g_acc[128], s);
    }
}

// ---------------- finalize + reset degree arrays for next replay ---------------------
__global__ void finalize_kernel(float* __restrict__ out) {
    int gidx = blockIdx.x * blockDim.x + threadIdx.x;
    int gstride = gridDim.x * blockDim.x;
    for (int j = gidx; j < N_EDGES; j += gstride) g_ecnt[j] = 0;
    for (int j = gidx; j < N_NODES; j += gstride) g_ncnt[j] = 0;
    if (blockIdx.x == 0 && threadIdx.x < 128)
        out[threadIdx.x] = g_acc[threadIdx.x] / g_acc[128];
}

// ---------------- launch -------------------------------------------------------------
extern "C" void kernel_launch(void* const* d_in, const int* in_sizes, int n_in,
                              void* d_out, int out_size) {
    const float* x       = (const float*)d_in[0];          // [100000, 300]
    const int*   nidx    = (const int*)d_in[1];
    const int*   eidx    = ((const int*)d_in[1]) + NNZ;
    const float* W1      = (const float*)d_in[2];          // [300,256]
    const float* b1      = (const float*)d_in[3];
    const float* W2      = (const float*)d_in[4];          // [256,256]
    const float* b2      = (const float*)d_in[5];
    const float* W3      = (const float*)d_in[6];          // [256,128]
    const float* b3      = (const float*)d_in[7];
    const float* attn_W  = (const float*)d_in[8];          // [128,1]
    const float* attn_b  = (const float*)d_in[9];          // [1]
    float* out = (float*)d_out;                            // [128]

    // CSR build (degree arrays zero at entry: static init / finalize epilogue)
    hist_kernel<<<2048, 256>>>(nidx, eidx);
    scan_kernel<<<2, 1024>>>();
    csr_kernel<<<2048, 256>>>(nidx, eidx);

    // Layer 1: eagg1 (fp32, lda 304) = mean x over members; ew1 = eagg1 @ W1
    agg_edge_x<<<7500, 256>>>(x, g_eagg);                  // <- ncu capture slot 4
    sgemm_kernel<<<dim3(157, 4), 256>>>(g_eagg, W1, g_ew, N_EDGES, 300, 256, LDA1);

    // Layer 2: zero eagg; scatter lrelu(h1) into eagg2; ew2 = eagg2 @ W2
    zero_eagg_kernel<<<2048, 256>>>(g_eagg);
    fuse_scatter_kernel<<<25000, 256>>>(g_ew, g_eagg, b1);
    sgemm_kernel<<<dim3(157, 4), 256>>>(g_eagg, W2, g_ew, N_EDGES, 256, 256, 256);

    // Layer 3: same with W3 (N=128)
    zero_eagg_kernel<<<2048, 256>>>(g_eagg);
    fuse_scatter_kernel<<<25000, 256>>>(g_ew, g_eagg, b2);
    sgemm_kernel<<<dim3(157, 2), 256>>>(g_eagg, W3, g_ew, N_EDGES, 256, 128, 256);

    // Attention pooling: h3 recomputed per node from ew3 (stride 128, L2-resident)
    logits_kernel<<<12500, 256>>>(g_ew, b3, attn_W, attn_b);
    maxred_kernel<<<1, 1024>>>(12500);
    accum_kernel<<<12500, 256>>>(g_ew, b3);
    finalize_kernel<<<512, 256>>>(out);
}

// round 15
// speedup vs baseline: 5.5730x; 1.3428x over previous
#include <cuda_runtime.h>
#include <cuda_fp16.h>

#define N_NODES 100000
#define N_EDGES 20000
#define NNZ     1600000
#define LDA1    304     // padded fp16 row stride for layer-1 K=300

// ---------------- scratch (device globals; zero-initialized at module load) ----------
// RULE: each array is accessed EITHER only via host-passed args OR only via device
// symbols — never both (host/device symbol resolutions differ on this toolchain).
__device__ __half          g_eagg[(size_t)N_EDGES * LDA1]; // edge-agg feats (12.2MB, host-arg)
__device__ __half          g_ew[(size_t)N_EDGES * 256];    // edge feats after W (10.2MB, host-arg)
__device__ __half          g_htmp[(size_t)N_NODES * 64];   // 64-col h slice (12.8MB, host-arg)
                                                           //  (also aliased as scatter cursors
                                                           //   during CSR build, host-arg)
__device__ int             g_ecnt[N_EDGES];                // degrees (device-symbol; zeroed by finalize)
__device__ int             g_ncnt[N_NODES];
__device__ int             g_estart[N_EDGES];              // CSR offsets (device-symbol)
__device__ int             g_nstart[N_NODES];
__device__ int             g_eitems[NNZ];                  // per-edge node lists (6.4MB, device-symbol)
__device__ unsigned short  g_nitems[NNZ];                  // per-node edge lists (3.2MB, device-symbol)
__device__ float           g_logits[N_NODES];
__device__ float           g_partmax[12500];
__device__ float           g_gmax;
__device__ float           g_acc[129];                     // [0..127] sum, [128]=Z

static __device__ __forceinline__ void acc_h4(float4& acc, uint2 raw) {
    float2 f0 = __half22float2(*reinterpret_cast<__half2*>(&raw.x));
    float2 f1 = __half22float2(*reinterpret_cast<__half2*>(&raw.y));
    acc.x += f0.x; acc.y += f0.y; acc.z += f1.x; acc.w += f1.y;
}
static __device__ __forceinline__ void acc_h2(float2& acc, unsigned raw) {
    float2 f = __half22float2(*reinterpret_cast<__half2*>(&raw));
    acc.x += f.x; acc.y += f.y;
}
static __device__ __forceinline__ uint2 pack_h4(float4 o) {
    __half2 v0 = __floats2half2_rn(o.x, o.y);
    __half2 v1 = __floats2half2_rn(o.z, o.w);
    uint2 pk;
    pk.x = *reinterpret_cast<unsigned*>(&v0);
    pk.y = *reinterpret_cast<unsigned*>(&v1);
    return pk;
}

// ---------------- degree histogram (cnt zero at entry: static init / finalize) -------
__global__ void hist_kernel(const int* __restrict__ nidx, const int* __restrict__ eidx) {
    int i = blockIdx.x * blockDim.x + threadIdx.x;
    int stride = gridDim.x * blockDim.x;
    for (int j = i; j < NNZ; j += stride) {
        atomicAdd(&g_ecnt[eidx[j]], 1);
        atomicAdd(&g_ncnt[nidx[j]], 1);
    }
}

// ---------------- exclusive scan: block 0 -> edges, block 1 -> nodes -----------------
// cursor arrays are carved (by the host) out of g_htmp, dead at this point.
__global__ void scan_kernel(int* __restrict__ ecur, int* __restrict__ ncur) {
    const bool edges = (blockIdx.x == 0);
    int*       cnt    = edges ? g_ecnt   : g_ncnt;
    int*       start  = edges ? g_estart : g_nstart;
    int*       cursor = edges ? ecur     : ncur;
    const int  n      = edges ? N_EDGES  : N_NODES;

    __shared__ int sh[1024];
    __shared__ int s_carry;
    if (threadIdx.x == 0) s_carry = 0;
    __syncthreads();
    for (int base = 0; base < n; base += 1024) {
        int i = base + threadIdx.x;
        int v = (i < n) ? cnt[i] : 0;
        sh[threadIdx.x] = v;
        __syncthreads();
        for (int off = 1; off < 1024; off <<= 1) {
            int t = 0;
            if (threadIdx.x >= off) t = sh[threadIdx.x - off];
            __syncthreads();
            if (threadIdx.x >= off) sh[threadIdx.x] += t;
            __syncthreads();
        }
        int carry = s_carry;
        int incl = sh[threadIdx.x];
        if (i < n) {
            int excl = carry + incl - v;
            start[i] = excl;
            cursor[i] = excl;
        }
        __syncthreads();
        if (threadIdx.x == 1023) s_carry = carry + sh[1023];
        __syncthreads();
    }
}

// ---------------- CSR scatter --------------------------------------------------------
__global__ void csr_kernel(const int* __restrict__ nidx, const int* __restrict__ eidx,
                           int* __restrict__ ecur, int* __restrict__ ncur) {
    int i = blockIdx.x * blockDim.x + threadIdx.x;
    int stride = gridDim.x * blockDim.x;
    for (int j = i; j < NNZ; j += stride) {
        int n = nidx[j];
        int e = eidx[j];
        int p = atomicAdd(&ecur[e], 1);
        g_eitems[p] = n;
        int q = atomicAdd(&ncur[n], 1);
        g_nitems[q] = (unsigned short)e;
    }
}

// ---------------- layer-1 edge aggregation: fp32 x -> fp16 eagg1 (stride LDA1) -------
// warp per (edge, 128-col chunk); 8 independent float4 gathers; zeroes pad cols.
__global__ __launch_bounds__(256) void agg_edge_x(const float* __restrict__ src,
                                                  __half* __restrict__ dst) {
    const int F = 300, CHUNKS = 3;
    int w = (blockIdx.x * blockDim.x + threadIdx.x) >> 5;
    int lane = threadIdx.x & 31;
    int row = w / CHUNKS;
    int ch  = w % CHUNKS;
    if (row >= N_EDGES) return;

    const int* __restrict__ lst = g_eitems + g_estart[row];
    int cnt = g_ecnt[row];

    int colbase = ch * 128 + lane * 4;
    const bool active = colbase < F;
    const float* __restrict__ sp = src + colbase;

    float4 acc = make_float4(0.f, 0.f, 0.f, 0.f);
    int i = 0;
    for (; i + 8 <= cnt; i += 8) {
        int idxreg = 0;
        if (lane < 8) idxreg = lst[i + lane];
        int ns[8];
#pragma unroll
        for (int k = 0; k < 8; k++) ns[k] = __shfl_sync(0xffffffffu, idxreg, k);
        float4 t[8];
#pragma unroll
        for (int k = 0; k < 8; k++) {
            t[k] = make_float4(0.f, 0.f, 0.f, 0.f);
            if (active) t[k] = *(const float4*)(sp + (size_t)ns[k] * F);
        }
#pragma unroll
        for (int k = 0; k < 8; k++) {
            acc.x += t[k].x; acc.y += t[k].y; acc.z += t[k].z; acc.w += t[k].w;
        }
    }
    for (; i < cnt; i++) {
        if (active) {
            float4 t = *(const float4*)(sp + (size_t)lst[i] * F);
            acc.x += t.x; acc.y += t.y; acc.z += t.z; acc.w += t.w;
        }
    }
    if (active) {
        float inv = (cnt > 0) ? 1.0f / (float)cnt : 0.0f;
        float4 o = make_float4(acc.x * inv, acc.y * inv, acc.z * inv, acc.w * inv);
        *(uint2*)(dst + (size_t)row * LDA1 + colbase) = pack_h4(o);
    } else if (colbase < LDA1) {
        *(uint2*)(dst + (size_t)row * LDA1 + colbase) = make_uint2(0u, 0u);
    }
}

// ---------------- node h-slice: htmp[n, 0:64] = lrelu(bias + mean ew[e', cols])[slice]
// warp per node; lane owns 2 cols (4B); MLP=8 gathers over the node's edge rows.
__global__ __launch_bounds__(256) void agg_node_chunk(const __half* __restrict__ ew,
                                                      __half* __restrict__ htmp,
                                                      const float* __restrict__ bias,
                                                      int chunk) {
    int node = (blockIdx.x * blockDim.x + threadIdx.x) >> 5;
    int lane = threadIdx.x & 31;
    if (node >= N_NODES) return;
    int s = g_nstart[node], cn = g_ncnt[node];

    int col = chunk * 64 + lane * 2;
    const __half* __restrict__ sp = ew + col;

    float2 acc = make_float2(0.f, 0.f);
    for (int j = 0; j < cn; j += 8) {
        int rem = cn - j; if (rem > 8) rem = 8;
        int er = 0;
        if (lane < rem) er = (int)g_nitems[s + j + lane];
        int es[8];
#pragma unroll
        for (int t = 0; t < 8; t++) es[t] = __shfl_sync(0xffffffffu, er, t);
        unsigned raw[8];
#pragma unroll
        for (int t = 0; t < 8; t++) {
            raw[t] = 0u;
            if (t < rem) raw[t] = *(const unsigned*)(sp + (size_t)es[t] * 256);
        }
#pragma unroll
        for (int t = 0; t < 8; t++) acc_h2(acc, raw[t]);
    }
    float inv = (cn > 0) ? 1.0f / (float)cn : 0.0f;
    float2 bb = *(const float2*)(bias + col);
    float2 h;
    h.x = acc.x * inv + bb.x;
    h.y = acc.y * inv + bb.y;
    h.x = (h.x > 0.f) ? h.x : 0.01f * h.x;
    h.y = (h.y > 0.f) ? h.y : 0.01f * h.y;
    __half2 v = __floats2half2_rn(h.x, h.y);
    *(unsigned*)(htmp + (size_t)node * 64 + lane * 2) = *reinterpret_cast<unsigned*>(&v);
}

// ---------------- edge slice aggregation: eagg[e, slice] = mean htmp over members ----
// warp per edge; lane owns 2 cols; MLP=8 128B row-gathers from htmp (stride 64).
__global__ __launch_bounds__(256) void agg_edge_chunk(const __half* __restrict__ htmp,
                                                      __half* __restrict__ eagg,
                                                      int chunk) {
    int row = (blockIdx.x * blockDim.x + threadIdx.x) >> 5;
    int lane = threadIdx.x & 31;
    if (row >= N_EDGES) return;

    const int* __restrict__ lst = g_eitems + g_estart[row];
    int cnt = g_ecnt[row];
    const __half* __restrict__ sp = htmp + lane * 2;

    float2 acc = make_float2(0.f, 0.f);
    for (int i = 0; i < cnt; i += 8) {
        int rem = cnt - i; if (rem > 8) rem = 8;
        int ir = 0;
        if (lane < rem) ir = lst[i + lane];
        int ns[8];
#pragma unroll
        for (int k = 0; k < 8; k++) ns[k] = __shfl_sync(0xffffffffu, ir, k);
        unsigned raw[8];
#pragma unroll
        for (int k = 0; k < 8; k++) {
            raw[k] = 0u;
            if (k < rem) raw[k] = *(const unsigned*)(sp + (size_t)ns[k] * 64);
        }
#pragma unroll
        for (int k = 0; k < 8; k++) acc_h2(acc, raw[k]);
    }
    float inv = (cnt > 0) ? 1.0f / (float)cnt : 0.0f;
    __half2 v = __floats2half2_rn(acc.x * inv, acc.y * inv);
    *(unsigned*)(eagg + (size_t)row * 256 + chunk * 64 + lane * 2) =
        *reinterpret_cast<unsigned*>(&v);
}

// ---------------- SGEMM: fp16 A (lda-padded), fp32 B, fp16 C, fp32 accum -------------
// BM=128, BN=64, BK=16, 256 threads, 8x4 per thread. A pad cols must be zero.
__global__ __launch_bounds__(256) void sgemm_kernel(const __half* __restrict__ A,
                                                    const float* __restrict__ B,
                                                    __half* __restrict__ C,
                                                    int M, int K, int N, int lda) {
    __shared__ float As[16][136];
    __shared__ float Bs[16][64];
    const int tid = threadIdx.x;
    const int bm = blockIdx.x * 128;
    const int bn = blockIdx.y * 64;
    const int a_row = tid >> 1;
    const int a_grp = (tid & 1) * 8;
    const int b_row = tid >> 4;
    const int b_col = (tid & 15) * 4;
    const int ty = tid >> 4;
    const int tx = tid & 15;
    float acc[8][4];
#pragma unroll
    for (int i = 0; i < 8; i++)
#pragma unroll
        for (int j = 0; j < 4; j++) acc[i][j] = 0.f;

    const bool arow_ok = (bm + a_row) < M;
    const __half* Ab = A + (size_t)(bm + a_row) * lda;

    for (int kt = 0; kt < K; kt += 16) {
        {
            uint4 raw = make_uint4(0u, 0u, 0u, 0u);
            if (arow_ok) raw = *(const uint4*)(Ab + kt + a_grp);
            const __half2* hp = reinterpret_cast<const __half2*>(&raw);
#pragma unroll
            for (int j = 0; j < 4; j++) {
                float2 f = __half22float2(hp[j]);
                As[a_grp + j * 2 + 0][a_row] = f.x;
                As[a_grp + j * 2 + 1][a_row] = f.y;
            }
        }
        {
            int k = kt + b_row;
            float4 bv = make_float4(0.f, 0.f, 0.f, 0.f);
            if (k < K) bv = *(const float4*)(B + (size_t)k * N + bn + b_col);
            *(float4*)&Bs[b_row][b_col] = bv;
        }
        __syncthreads();
#pragma unroll
        for (int k = 0; k < 16; k++) {
            float4 a0 = *(const float4*)&As[k][ty * 8];
            float4 a1 = *(const float4*)&As[k][ty * 8 + 4];
            float4 bv = *(const float4*)&Bs[k][tx * 4];
            float a[8] = {a0.x, a0.y, a0.z, a0.w, a1.x, a1.y, a1.z, a1.w};
            float b[4] = {bv.x, bv.y, bv.z, bv.w};
#pragma unroll
            for (int i = 0; i < 8; i++)
#pragma unroll
                for (int j = 0; j < 4; j++) acc[i][j] += a[i] * b[j];
        }
        __syncthreads();
    }
#pragma unroll
    for (int i = 0; i < 8; i++) {
        int r = bm + ty * 8 + i;
        if (r < M) {
            float4 o = make_float4(acc[i][0], acc[i][1], acc[i][2], acc[i][3]);
            *(uint2*)(C + (size_t)r * N + bn + tx * 4) = pack_h4(o);
        }
    }
}

// ---------------- h3 on the fly: mean of node's ew3 rows (stride 128) + b3 -----------
static __device__ __forceinline__ float4 node_h3(const __half* __restrict__ ew3,
                                                 const float* __restrict__ b3,
                                                 int node, int lane) {
    int s = g_nstart[node], cn = g_ncnt[node];
    const __half* sp = ew3 + lane * 4;
    float4 acc = make_float4(0.f, 0.f, 0.f, 0.f);
    for (int j = 0; j < cn; j += 8) {
        int rem = cn - j; if (rem > 8) rem = 8;
        int er = 0;
        if (lane < rem) er = (int)g_nitems[s + j + lane];
        int es[8];
#pragma unroll
        for (int t = 0; t < 8; t++) es[t] = __shfl_sync(0xffffffffu, er, t);
        uint2 raw[8];
#pragma unroll
        for (int t = 0; t < 8; t++) {
            raw[t] = make_uint2(0u, 0u);
            if (t < rem) raw[t] = *(const uint2*)(sp + (size_t)es[t] * 128);
        }
#pragma unroll
        for (int t = 0; t < 8; t++) acc_h4(acc, raw[t]);
    }
    float inv = (cn > 0) ? 1.0f / (float)cn : 0.0f;
    float4 bb = *(const float4*)(b3 + lane * 4);
    return make_float4(acc.x * inv + bb.x, acc.y * inv + bb.y,
                       acc.z * inv + bb.z, acc.w * inv + bb.w);
}

// ---------------- logits pass: warp per node ----------------------------------------
__global__ __launch_bounds__(256) void logits_kernel(const __half* __restrict__ ew3,
                                                     const float* __restrict__ b3,
                                                     const float* __restrict__ aw,
                                                     const float* __restrict__ ab) {
    __shared__ float smax[8];
    int gw = (blockIdx.x * blockDim.x + threadIdx.x) >> 5;
    int lane = threadIdx.x & 31;
    float lg = -1e30f;
    if (gw < N_NODES) {
        float4 h = node_h3(ew3, b3, gw, lane);
        float4 wv = ((const float4*)aw)[lane];
        float d = h.x * wv.x + h.y * wv.y + h.z * wv.z + h.w * wv.w;
#pragma unroll
        for (int off = 16; off > 0; off >>= 1) d += __shfl_xor_sync(0xffffffffu, d, off);
        d += ab[0];
        if (lane == 0) g_logits[gw] = d;
        lg = d;
    }
    int wl = threadIdx.x >> 5;
    if (lane == 0) smax[wl] = lg;
    __syncthreads();
    if (threadIdx.x == 0) {
        float m = smax[0];
#pragma unroll
        for (int j = 1; j < 8; j++) m = fmaxf(m, smax[j]);
        g_partmax[blockIdx.x] = m;
    }
}

__global__ void maxred_kernel(int nparts) {
    __shared__ float sm[32];
    if (threadIdx.x < 129) g_acc[threadIdx.x] = 0.0f;
    float m = -1e30f;
    for (int i = threadIdx.x; i < nparts; i += 1024) m = fmaxf(m, g_partmax[i]);
#pragma unroll
    for (int off = 16; off > 0; off >>= 1) m = fmaxf(m, __shfl_xor_sync(0xffffffffu, m, off));
    if ((threadIdx.x & 31) == 0) sm[threadIdx.x >> 5] = m;
    __syncthreads();
    if (threadIdx.x < 32) {
        float v = sm[threadIdx.x];
#pragma unroll
        for (int off = 16; off > 0; off >>= 1) v = fmaxf(v, __shfl_xor_sync(0xffffffffu, v, off));
        if (threadIdx.x == 0) g_gmax = v;
    }
}

// ---------------- accumulate pass: warp per node, block-reduce, atomic ---------------
__global__ __launch_bounds__(256) void accum_kernel(const __half* __restrict__ ew3,
                                                    const float* __restrict__ b3) {
    __shared__ float sred[8][128];
    __shared__ float sz[8];
    int wl = threadIdx.x >> 5;
    int lane = threadIdx.x & 31;
    int gw = (blockIdx.x * blockDim.x + threadIdx.x) >> 5;
    float gmax = g_gmax;
    float4 wacc = make_float4(0.f, 0.f, 0.f, 0.f);
    float z = 0.f;
    if (gw < N_NODES) {
        float4 h = node_h3(ew3, b3, gw, lane);
        float wgt = expf(g_logits[gw] - gmax);
        wacc.x = wgt * h.x; wacc.y = wgt * h.y; wacc.z = wgt * h.z; wacc.w = wgt * h.w;
        z = wgt;
    }
    *(float4*)&sred[wl][lane * 4] = wacc;
    if (lane == 0) sz[wl] = z;
    __syncthreads();
    if (threadIdx.x < 128) {
        float s = 0.f;
#pragma unroll
        for (int j = 0; j < 8; j++) s += sred[j][threadIdx.x];
        atomicAdd(&g_acc[threadIdx.x], s);
    } else if (threadIdx.x == 128) {
        float s = 0.f;
#pragma unroll
        for (int j = 0; j < 8; j++) s += sz[j];
        atomicAdd(&g_acc[128], s);
    }
}

// ---------------- finalize + reset degree arrays for next replay ---------------------
__global__ void finalize_kernel(float* __restrict__ out) {
    int gidx = blockIdx.x * blockDim.x + threadIdx.x;
    int gstride = gridDim.x * blockDim.x;
    for (int j = gidx; j < N_EDGES; j += gstride) g_ecnt[j] = 0;
    for (int j = gidx; j < N_NODES; j += gstride) g_ncnt[j] = 0;
    if (blockIdx.x == 0 && threadIdx.x < 128)
        out[threadIdx.x] = g_acc[threadIdx.x] / g_acc[128];
}

// ---------------- launch -------------------------------------------------------------
extern "C" void kernel_launch(void* const* d_in, const int* in_sizes, int n_in,
                              void* d_out, int out_size) {
    const float* x       = (const float*)d_in[0];          // [100000, 300]
    const int*   nidx    = (const int*)d_in[1];
    const int*   eidx    = ((const int*)d_in[1]) + NNZ;
    const float* W1      = (const float*)d_in[2];          // [300,256]
    const float* b1      = (const float*)d_in[3];
    const float* W2      = (const float*)d_in[4];          // [256,256]
    const float* b2      = (const float*)d_in[5];
    const float* W3      = (const float*)d_in[6];          // [256,128]
    const float* b3      = (const float*)d_in[7];
    const float* attn_W  = (const float*)d_in[8];          // [128,1]
    const float* attn_b  = (const float*)d_in[9];          // [1]
    float* out = (float*)d_out;                            // [128]

    // scatter cursors live in g_htmp during CSR build (htmp dead until layer 2)
    int* ecur = (int*)g_htmp;
    int* ncur = ((int*)g_htmp) + N_EDGES;

    // CSR build (degree arrays zero at entry: static init / finalize epilogue)
    hist_kernel<<<2048, 256>>>(nidx, eidx);
    scan_kernel<<<2, 1024>>>(ecur, ncur);
    csr_kernel<<<2048, 256>>>(nidx, eidx, ecur, ncur);

    // Layer 1: eagg1 (fp16, lda 304) = mean x over members; ew1 = eagg1 @ W1
    agg_edge_x<<<7500, 256>>>(x, g_eagg);                  // <- ncu capture slot 4
    sgemm_kernel<<<dim3(157, 4), 256>>>(g_eagg, W1, g_ew, N_EDGES, 300, 256, LDA1);

    // Layer 2: 64-col slices: h1 slice -> htmp -> eagg2 slice; then ew2 = eagg2 @ W2
    for (int c = 0; c < 4; c++) {
        agg_node_chunk<<<12500, 256>>>(g_ew, g_htmp, b1, c);
        agg_edge_chunk<<<2500, 256>>>(g_htmp, g_eagg, c);
    }
    sgemm_kernel<<<dim3(157, 4), 256>>>(g_eagg, W2, g_ew, N_EDGES, 256, 256, 256);

    // Layer 3: same with b2/W3 (N=128)
    for (int c = 0; c < 4; c++) {
        agg_node_chunk<<<12500, 256>>>(g_ew, g_htmp, b2, c);
        agg_edge_chunk<<<2500, 256>>>(g_htmp, g_eagg, c);
    }
    sgemm_kernel<<<dim3(157, 2), 256>>>(g_eagg, W3, g_ew, N_EDGES, 256, 128, 256);

    // Attention pooling: h3 recomputed per node from ew3 (stride 128, L2-resident)
    logits_kernel<<<12500, 256>>>(g_ew, b3, attn_W, attn_b);
    maxred_kernel<<<1, 1024>>>(12500);
    accum_kernel<<<12500, 256>>>(g_ew, b3);
    finalize_kernel<<<512, 256>>>(out);
}

// round 16
// speedup vs baseline: 6.6935x; 1.2011x over previous
#include <cuda_runtime.h>
#include <cuda_fp16.h>

#define N_NODES 100000
#define N_EDGES 20000
#define NNZ     1600000
#define LDA1    304     // padded fp16 row stride for layer-1 K=300

// ---------------- scratch (device globals; zero-initialized at module load) ----------
// RULE: each array is accessed EITHER only via host-passed args OR only via device
// symbols — never both (host/device symbol resolutions differ on this toolchain).
__device__ __half          g_eagg[(size_t)N_EDGES * LDA1]; // edge-agg feats (12.2MB, host-arg)
__device__ __half          g_ew[(size_t)N_EDGES * 256];    // edge feats after W (10.2MB, host-arg)
__device__ __half          g_h[(size_t)N_NODES * 256];     // h1/h2 (51.2MB, host-arg; front
                                                           //  480KB doubles as CSR cursors)
__device__ int             g_ecnt[N_EDGES];                // degrees (device-symbol; zeroed by finalize)
__device__ int             g_ncnt[N_NODES];
__device__ int             g_estart[N_EDGES];              // CSR offsets (device-symbol)
__device__ int             g_nstart[N_NODES];
__device__ int             g_eitems[NNZ];                  // per-edge node lists (6.4MB, device-symbol)
__device__ unsigned short  g_nitems[NNZ];                  // per-node edge lists (3.2MB, device-symbol)
__device__ float           g_acc[129];                     // [0..127] sum, [128]=Z (zeroed by finalize)

static __device__ __forceinline__ void acc_h4(float4& acc, uint2 raw) {
    float2 f0 = __half22float2(*reinterpret_cast<__half2*>(&raw.x));
    float2 f1 = __half22float2(*reinterpret_cast<__half2*>(&raw.y));
    acc.x += f0.x; acc.y += f0.y; acc.z += f1.x; acc.w += f1.y;
}
static __device__ __forceinline__ uint2 pack_h4(float4 o) {
    __half2 v0 = __floats2half2_rn(o.x, o.y);
    __half2 v1 = __floats2half2_rn(o.z, o.w);
    uint2 pk;
    pk.x = *reinterpret_cast<unsigned*>(&v0);
    pk.y = *reinterpret_cast<unsigned*>(&v1);
    return pk;
}

// ---------------- degree histogram (cnt zero at entry: static init / finalize) -------
__global__ void hist_kernel(const int* __restrict__ nidx, const int* __restrict__ eidx) {
    int i = blockIdx.x * blockDim.x + threadIdx.x;
    int stride = gridDim.x * blockDim.x;
    for (int j = i; j < NNZ; j += stride) {
        atomicAdd(&g_ecnt[eidx[j]], 1);
        atomicAdd(&g_ncnt[nidx[j]], 1);
    }
}

// ---------------- exclusive scan: block 0 -> edges, block 1 -> nodes -----------------
// cursor arrays are carved (by the host) out of g_h, dead at this point.
__global__ void scan_kernel(int* __restrict__ ecur, int* __restrict__ ncur) {
    const bool edges = (blockIdx.x == 0);
    int*       cnt    = edges ? g_ecnt   : g_ncnt;
    int*       start  = edges ? g_estart : g_nstart;
    int*       cursor = edges ? ecur     : ncur;
    const int  n      = edges ? N_EDGES  : N_NODES;

    __shared__ int sh[1024];
    __shared__ int s_carry;
    if (threadIdx.x == 0) s_carry = 0;
    __syncthreads();
    for (int base = 0; base < n; base += 1024) {
        int i = base + threadIdx.x;
        int v = (i < n) ? cnt[i] : 0;
        sh[threadIdx.x] = v;
        __syncthreads();
        for (int off = 1; off < 1024; off <<= 1) {
            int t = 0;
            if (threadIdx.x >= off) t = sh[threadIdx.x - off];
            __syncthreads();
            if (threadIdx.x >= off) sh[threadIdx.x] += t;
            __syncthreads();
        }
        int carry = s_carry;
        int incl = sh[threadIdx.x];
        if (i < n) {
            int excl = carry + incl - v;
            start[i] = excl;
            cursor[i] = excl;
        }
        __syncthreads();
        if (threadIdx.x == 1023) s_carry = carry + sh[1023];
        __syncthreads();
    }
}

// ---------------- CSR scatter --------------------------------------------------------
__global__ void csr_kernel(const int* __restrict__ nidx, const int* __restrict__ eidx,
                           int* __restrict__ ecur, int* __restrict__ ncur) {
    int i = blockIdx.x * blockDim.x + threadIdx.x;
    int stride = gridDim.x * blockDim.x;
    for (int j = i; j < NNZ; j += stride) {
        int n = nidx[j];
        int e = eidx[j];
        int p = atomicAdd(&ecur[e], 1);
        g_eitems[p] = n;
        int q = atomicAdd(&ncur[n], 1);
        g_nitems[q] = (unsigned short)e;
    }
}

// ---------------- layer-1 edge aggregation: fp32 x -> fp16 eagg1 (stride LDA1) -------
__global__ __launch_bounds__(256) void agg_edge_x(const float* __restrict__ src,
                                                  __half* __restrict__ dst) {
    const int F = 300, CHUNKS = 3;
    int w = (blockIdx.x * blockDim.x + threadIdx.x) >> 5;
    int lane = threadIdx.x & 31;
    int row = w / CHUNKS;
    int ch  = w % CHUNKS;
    if (row >= N_EDGES) return;

    const int* __restrict__ lst = g_eitems + g_estart[row];
    int cnt = g_ecnt[row];

    int colbase = ch * 128 + lane * 4;
    const bool active = colbase < F;
    const float* __restrict__ sp = src + colbase;

    float4 acc = make_float4(0.f, 0.f, 0.f, 0.f);
    int i = 0;
    for (; i + 8 <= cnt; i += 8) {
        int idxreg = 0;
        if (lane < 8) idxreg = lst[i + lane];
        int ns[8];
#pragma unroll
        for (int k = 0; k < 8; k++) ns[k] = __shfl_sync(0xffffffffu, idxreg, k);
        float4 t[8];
#pragma unroll
        for (int k = 0; k < 8; k++) {
            t[k] = make_float4(0.f, 0.f, 0.f, 0.f);
            if (active) t[k] = *(const float4*)(sp + (size_t)ns[k] * F);
        }
#pragma unroll
        for (int k = 0; k < 8; k++) {
            acc.x += t[k].x; acc.y += t[k].y; acc.z += t[k].z; acc.w += t[k].w;
        }
    }
    for (; i < cnt; i++) {
        if (active) {
            float4 t = *(const float4*)(sp + (size_t)lst[i] * F);
            acc.x += t.x; acc.y += t.y; acc.z += t.z; acc.w += t.w;
        }
    }
    if (active) {
        float inv = (cnt > 0) ? 1.0f / (float)cnt : 0.0f;
        float4 o = make_float4(acc.x * inv, acc.y * inv, acc.z * inv, acc.w * inv);
        *(uint2*)(dst + (size_t)row * LDA1 + colbase) = pack_h4(o);
    } else if (colbase < LDA1) {
        *(uint2*)(dst + (size_t)row * LDA1 + colbase) = make_uint2(0u, 0u);
    }
}

// ---------------- node aggregation (layers 1-2): fp16 ew -> fp16 h, +bias, lrelu -----
__global__ __launch_bounds__(256) void agg_node_f16(const __half* __restrict__ src,
                                                    __half* __restrict__ dst,
                                                    const float* __restrict__ bias) {
    int w = (blockIdx.x * blockDim.x + threadIdx.x) >> 5;
    int lane = threadIdx.x & 31;
    int row = w >> 1;                  // node (2 chunks of 128 cols)
    int ch  = w & 1;
    if (row >= N_NODES) return;

    const unsigned short* __restrict__ lst = g_nitems + g_nstart[row];
    int cnt = g_ncnt[row];

    int colbase = ch * 128 + lane * 4;
    const __half* __restrict__ sp = src + colbase;

    float4 acc = make_float4(0.f, 0.f, 0.f, 0.f);
    int i = 0;
    for (; i + 8 <= cnt; i += 8) {
        int idxreg = 0;
        if (lane < 8) idxreg = (int)lst[i + lane];
        int ns[8];
#pragma unroll
        for (int k = 0; k < 8; k++) ns[k] = __shfl_sync(0xffffffffu, idxreg, k);
        uint2 raw[8];
#pragma unroll
        for (int k = 0; k < 8; k++) raw[k] = *(const uint2*)(sp + (size_t)ns[k] * 256);
#pragma unroll
        for (int k = 0; k < 8; k++) acc_h4(acc, raw[k]);
    }
    for (; i < cnt; i++) {
        uint2 raw = *(const uint2*)(sp + (size_t)lst[i] * 256);
        acc_h4(acc, raw);
    }
    float inv = (cnt > 0) ? 1.0f / (float)cnt : 0.0f;
    float4 bb = *(const float4*)(bias + colbase);
    float4 o;
    o.x = acc.x * inv + bb.x;
    o.y = acc.y * inv + bb.y;
    o.z = acc.z * inv + bb.z;
    o.w = acc.w * inv + bb.w;
    o.x = (o.x > 0.f) ? o.x : 0.01f * o.x;
    o.y = (o.y > 0.f) ? o.y : 0.01f * o.y;
    o.z = (o.z > 0.f) ? o.z : 0.01f * o.z;
    o.w = (o.w > 0.f) ? o.w : 0.01f * o.w;
    *(uint2*)(dst + (size_t)row * 256 + colbase) = pack_h4(o);
}

// ---------------- edge aggregation from fp16 h (stride 256) -> fp16 eagg -------------
__global__ __launch_bounds__(256) void agg_edge_h(const __half* __restrict__ src,
                                                  __half* __restrict__ dst) {
    int w = (blockIdx.x * blockDim.x + threadIdx.x) >> 5;
    int lane = threadIdx.x & 31;
    int row = w >> 1;
    int ch  = w & 1;
    if (row >= N_EDGES) return;

    const int* __restrict__ lst = g_eitems + g_estart[row];
    int cnt = g_ecnt[row];

    int colbase = ch * 128 + lane * 4;
    const __half* __restrict__ sp = src + colbase;

    float4 acc = make_float4(0.f, 0.f, 0.f, 0.f);
    int i = 0;
    for (; i + 8 <= cnt; i += 8) {
        int idxreg = 0;
        if (lane < 8) idxreg = lst[i + lane];
        int ns[8];
#pragma unroll
        for (int k = 0; k < 8; k++) ns[k] = __shfl_sync(0xffffffffu, idxreg, k);
        uint2 raw[8];
#pragma unroll
        for (int k = 0; k < 8; k++) raw[k] = *(const uint2*)(sp + (size_t)ns[k] * 256);
#pragma unroll
        for (int k = 0; k < 8; k++) acc_h4(acc, raw[k]);
    }
    for (; i < cnt; i++) {
        uint2 raw = *(const uint2*)(sp + (size_t)lst[i] * 256);
        acc_h4(acc, raw);
    }
    float inv = (cnt > 0) ? 1.0f / (float)cnt : 0.0f;
    float4 o = make_float4(acc.x * inv, acc.y * inv, acc.z * inv, acc.w * inv);
    *(uint2*)(dst + (size_t)row * 256 + colbase) = pack_h4(o);
}

// ---------------- SGEMM: fp16 A (lda-padded), fp32 B, fp16 C, fp32 accum -------------
__global__ __launch_bounds__(256) void sgemm_kernel(const __half* __restrict__ A,
                                                    const float* __restrict__ B,
                                                    __half* __restrict__ C,
                                                    int M, int K, int N, int lda) {
    __shared__ float As[16][136];
    __shared__ float Bs[16][64];
    const int tid = threadIdx.x;
    const int bm = blockIdx.x * 128;
    const int bn = blockIdx.y * 64;
    const int a_row = tid >> 1;
    const int a_grp = (tid & 1) * 8;
    const int b_row = tid >> 4;
    const int b_col = (tid & 15) * 4;
    const int ty = tid >> 4;
    const int tx = tid & 15;
    float acc[8][4];
#pragma unroll
    for (int i = 0; i < 8; i++)
#pragma unroll
        for (int j = 0; j < 4; j++) acc[i][j] = 0.f;

    const bool arow_ok = (bm + a_row) < M;
    const __half* Ab = A + (size_t)(bm + a_row) * lda;

    for (int kt = 0; kt < K; kt += 16) {
        {
            uint4 raw = make_uint4(0u, 0u, 0u, 0u);
            if (arow_ok) raw = *(const uint4*)(Ab + kt + a_grp);
            const __half2* hp = reinterpret_cast<const __half2*>(&raw);
#pragma unroll
            for (int j = 0; j < 4; j++) {
                float2 f = __half22float2(hp[j]);
                As[a_grp + j * 2 + 0][a_row] = f.x;
                As[a_grp + j * 2 + 1][a_row] = f.y;
            }
        }
        {
            int k = kt + b_row;
            float4 bv = make_float4(0.f, 0.f, 0.f, 0.f);
            if (k < K) bv = *(const float4*)(B + (size_t)k * N + bn + b_col);
            *(float4*)&Bs[b_row][b_col] = bv;
        }
        __syncthreads();
#pragma unroll
        for (int k = 0; k < 16; k++) {
            float4 a0 = *(const float4*)&As[k][ty * 8];
            float4 a1 = *(const float4*)&As[k][ty * 8 + 4];
            float4 bv = *(const float4*)&Bs[k][tx * 4];
            float a[8] = {a0.x, a0.y, a0.z, a0.w, a1.x, a1.y, a1.z, a1.w};
            float b[4] = {bv.x, bv.y, bv.z, bv.w};
#pragma unroll
            for (int i = 0; i < 8; i++)
#pragma unroll
                for (int j = 0; j < 4; j++) acc[i][j] += a[i] * b[j];
        }
        __syncthreads();
    }
#pragma unroll
    for (int i = 0; i < 8; i++) {
        int r = bm + ty * 8 + i;
        if (r < M) {
            float4 o = make_float4(acc[i][0], acc[i][1], acc[i][2], acc[i][3]);
            *(uint2*)(C + (size_t)r * N + bn + tx * 4) = pack_h4(o);
        }
    }
}

// ---------------- fused attention epilogue ------------------------------------------
// warp per node: h3 = b3 + mean of node's ew3 rows (stride 128, L2-resident);
// logit = h3 . attn_W + attn_b  (bounded, no max-subtraction needed);
// w = exp(logit); block-reduce w*h3 and w; atomicAdd into g_acc.
__global__ __launch_bounds__(256) void epi_kernel(const __half* __restrict__ ew3,
                                                  const float* __restrict__ b3,
                                                  const float* __restrict__ aw,
                                                  const float* __restrict__ ab) {
    __shared__ float sred[8][128];
    __shared__ float sz[8];
    int wl = threadIdx.x >> 5;
    int lane = threadIdx.x & 31;
    int node = (blockIdx.x * blockDim.x + threadIdx.x) >> 5;

    float4 wacc = make_float4(0.f, 0.f, 0.f, 0.f);
    float z = 0.f;
    if (node < N_NODES) {
        int s = g_nstart[node], cn = g_ncnt[node];
        const __half* sp = ew3 + lane * 4;
        float4 acc = make_float4(0.f, 0.f, 0.f, 0.f);
        for (int j = 0; j < cn; j += 8) {
            int rem = cn - j; if (rem > 8) rem = 8;
            int er = 0;
            if (lane < rem) er = (int)g_nitems[s + j + lane];
            int es[8];
#pragma unroll
            for (int t = 0; t < 8; t++) es[t] = __shfl_sync(0xffffffffu, er, t);
            uint2 raw[8];
#pragma unroll
            for (int t = 0; t < 8; t++) {
                raw[t] = make_uint2(0u, 0u);
                if (t < rem) raw[t] = *(const uint2*)(sp + (size_t)es[t] * 128);
            }
#pragma unroll
            for (int t = 0; t < 8; t++) acc_h4(acc, raw[t]);
        }
        float inv = (cn > 0) ? 1.0f / (float)cn : 0.0f;
        float4 bb = *(const float4*)(b3 + lane * 4);
        float4 h = make_float4(acc.x * inv + bb.x, acc.y * inv + bb.y,
                               acc.z * inv + bb.z, acc.w * inv + bb.w);
        float4 wv = ((const float4*)aw)[lane];
        float d = h.x * wv.x + h.y * wv.y + h.z * wv.z + h.w * wv.w;
#pragma unroll
        for (int off = 16; off > 0; off >>= 1) d += __shfl_xor_sync(0xffffffffu, d, off);
        d += ab[0];
        float w = expf(d);                       // logits bounded; no max needed
        wacc = make_float4(w * h.x, w * h.y, w * h.z, w * h.w);
        z = w;
    }
    *(float4*)&sred[wl][lane * 4] = wacc;
    if (lane == 0) sz[wl] = z;
    __syncthreads();
    if (threadIdx.x < 128) {
        float s = 0.f;
#pragma unroll
        for (int j = 0; j < 8; j++) s += sred[j][threadIdx.x];
        atomicAdd(&g_acc[threadIdx.x], s);
    } else if (threadIdx.x == 128) {
        float s = 0.f;
#pragma unroll
        for (int j = 0; j < 8; j++) s += sz[j];
        atomicAdd(&g_acc[128], s);
    }
}

// ---------------- finalize: out = acc/Z; reset degree arrays + acc for next replay ---
__global__ void finalize_kernel(float* __restrict__ out) {
    int gidx = blockIdx.x * blockDim.x + threadIdx.x;
    int gstride = gridDim.x * blockDim.x;
    for (int j = gidx; j < N_EDGES; j += gstride) g_ecnt[j] = 0;
    for (int j = gidx; j < N_NODES; j += gstride) g_ncnt[j] = 0;
    if (blockIdx.x == 0 && threadIdx.x < 129) {
        float v = g_acc[threadIdx.x];
        float z = g_acc[128];
        __syncthreads();
        if (threadIdx.x < 128) out[threadIdx.x] = v / z;
        g_acc[threadIdx.x] = 0.0f;
    }
}

// ---------------- launch -------------------------------------------------------------
extern "C" void kernel_launch(void* const* d_in, const int* in_sizes, int n_in,
                              void* d_out, int out_size) {
    const float* x       = (const float*)d_in[0];          // [100000, 300]
    const int*   nidx    = (const int*)d_in[1];
    const int*   eidx    = ((const int*)d_in[1]) + NNZ;
    const float* W1      = (const float*)d_in[2];          // [300,256]
    const float* b1      = (const float*)d_in[3];
    const float* W2      = (const float*)d_in[4];          // [256,256]
    const float* b2      = (const float*)d_in[5];
    const float* W3      = (const float*)d_in[6];          // [256,128]
    const float* b3      = (const float*)d_in[7];
    const float* attn_W  = (const float*)d_in[8];          // [128,1]
    const float* attn_b  = (const float*)d_in[9];          // [1]
    float* out = (float*)d_out;                            // [128]

    // scatter cursors live in the front of g_h (dead until layer-1 agg_node writes it)
    int* ecur = (int*)g_h;
    int* ncur = ((int*)g_h) + N_EDGES;

    // CSR build (degree arrays zero at entry: static init / finalize epilogue)
    hist_kernel<<<2048, 256>>>(nidx, eidx);
    scan_kernel<<<2, 1024>>>(ecur, ncur);
    csr_kernel<<<2048, 256>>>(nidx, eidx, ecur, ncur);

    // Layer 1
    agg_edge_x<<<7500, 256>>>(x, g_eagg);                  // <- ncu capture slot 4
    sgemm_kernel<<<dim3(157, 4), 256>>>(g_eagg, W1, g_ew, N_EDGES, 300, 256, LDA1);
    agg_node_f16<<<25000, 256>>>(g_ew, g_h, b1);           // h1

    // Layer 2
    agg_edge_h<<<5000, 256>>>(g_h, g_eagg);
    sgemm_kernel<<<dim3(157, 4), 256>>>(g_eagg, W2, g_ew, N_EDGES, 256, 256, 256);
    agg_node_f16<<<25000, 256>>>(g_ew, g_h, b2);           // h2

    // Layer 3 (h3 never materialized — epilogue recomputes from ew3)
    agg_edge_h<<<5000, 256>>>(g_h, g_eagg);
    sgemm_kernel<<<dim3(157, 2), 256>>>(g_eagg, W3, g_ew, N_EDGES, 256, 128, 256);

    // Fused attention pooling (2 launches)
    epi_kernel<<<12500, 256>>>(g_ew, b3, attn_W, attn_b);
    finalize_kernel<<<512, 256>>>(out);
}